// round 13
// baseline (speedup 1.0000x reference)
#include <cuda_runtime.h>
#include <cuda_fp16.h>
#include <math.h>
#include <cstdint>

#define D_MODEL 2048
#define NHEADS  16
#define DK      128
#define BATCH   2
#define SEQ     2048
#define ROWS    (BATCH * SEQ)     // 4096
#define QKV_N   (3 * D_MODEL)     // 6144

// ---------------------------------------------------------------------------
// Scratch (device globals — no cudaMalloc allowed)
// ---------------------------------------------------------------------------
__device__ __half g_qkv_hi[ROWS * QKV_N];        // QKV (fp16)
__device__ __half g_a_hi[ROWS * D_MODEL];        // x fp16, then attn-out fp16
__device__ __half g_wq_h[QKV_N * D_MODEL];       // W_qkv^T fp16
__device__ __half g_wo_h[D_MODEL * D_MODEL];     // W_out^T fp16

// ---------------------------------------------------------------------------
// Base-target PTX helpers (virtual target is compute_103 — no tcgen05)
// ---------------------------------------------------------------------------
__device__ __forceinline__ uint32_t smem_u32(const void* p) {
    uint32_t a;
    asm("{ .reg .u64 t; cvta.to.shared.u64 t, %1; cvt.u32.u64 %0, t; }" : "=r"(a) : "l"(p));
    return a;
}
__device__ __forceinline__ void cp_async16(uint32_t saddr, const void* gaddr) {
    asm volatile("cp.async.cg.shared.global [%0], [%1], 16;" :: "r"(saddr), "l"(gaddr));
}
#define CP_COMMIT() asm volatile("cp.async.commit_group;" ::: "memory")
#define CP_WAIT(N)  asm volatile("cp.async.wait_group %0;" :: "n"(N) : "memory")

__device__ __forceinline__ void ldmx4(uint32_t* r, uint32_t addr) {
    asm volatile("ldmatrix.sync.aligned.m8n8.x4.shared.b16 {%0,%1,%2,%3}, [%4];"
                 : "=r"(r[0]), "=r"(r[1]), "=r"(r[2]), "=r"(r[3]) : "r"(addr));
}
__device__ __forceinline__ void ldmx4t(uint32_t* r, uint32_t addr) {
    asm volatile("ldmatrix.sync.aligned.m8n8.x4.trans.shared.b16 {%0,%1,%2,%3}, [%4];"
                 : "=r"(r[0]), "=r"(r[1]), "=r"(r[2]), "=r"(r[3]) : "r"(addr));
}
__device__ __forceinline__ void mma_fp16(float* d, const uint32_t* a, const uint32_t* b) {
    asm volatile(
        "mma.sync.aligned.m16n8k16.row.col.f32.f16.f16.f32 "
        "{%0,%1,%2,%3}, {%4,%5,%6,%7}, {%8,%9}, {%0,%1,%2,%3};"
        : "+f"(d[0]), "+f"(d[1]), "+f"(d[2]), "+f"(d[3])
        : "r"(a[0]), "r"(a[1]), "r"(a[2]), "r"(a[3]), "r"(b[0]), "r"(b[1]));
}

__device__ __forceinline__ uint32_t pack2h(float x, float y) {
    __half2 hh = __halves2half2(__float2half(x), __float2half(y));
    return *(uint32_t*)&hh;
}

// 128B-row smem tile swizzle (8 x 16B chunks per row): chunk ^= row&7
__device__ __forceinline__ uint32_t gsw(int r, int c) {
    return (uint32_t)(r * 128 + ((c ^ (r & 7)) << 4));
}
// Attention smem tile: rows of 128 fp16 (256B = 16 x 16B chunks): chunk ^= row&7
__device__ __forceinline__ uint32_t asw(int row, int ch) {
    return (uint32_t)(row * 256 + ((ch ^ (row & 7)) << 4));
}

// ---------------------------------------------------------------------------
// fp32 -> fp16 convert
__global__ void convert_half_kernel(const float* __restrict__ in,
                                    __half* __restrict__ hi, int n4)
{
    int i = blockIdx.x * blockDim.x + threadIdx.x;
    if (i >= n4) return;
    float4 v = ((const float4*)in)[i];
    ((uint32_t*)hi)[2*i]   = pack2h(v.x, v.y);
    ((uint32_t*)hi)[2*i+1] = pack2h(v.z, v.w);
}

// W[K,N] fp32 -> Wt[N,K] fp16
__global__ void transpose_half_kernel(const float* __restrict__ W,
                                      __half* __restrict__ Th,
                                      int K, int N)
{
    __shared__ float t[32][33];
    int k0 = blockIdx.y * 32, n0 = blockIdx.x * 32;
    #pragma unroll
    for (int i = threadIdx.y; i < 32; i += 8)
        t[i][threadIdx.x] = W[(size_t)(k0 + i) * N + n0 + threadIdx.x];
    __syncthreads();
    #pragma unroll
    for (int i = threadIdx.y; i < 32; i += 8)
        Th[(size_t)(n0 + i) * K + k0 + threadIdx.x] = __float2half(t[threadIdx.x][i]);
}

// ---------------------------------------------------------------------------
// HMMA GEMM: C[M,N] = A[M,K] @ Bt[N,K]^T + bias   (fp16 x fp16, fp32 acc)
// CTA 128x128, 4 warps (2x2), warp tile 64x64, BK=64, 3-stage pipeline.
// ---------------------------------------------------------------------------
#define GM_BK    64
#define STAGES   3
#define TILE_B   16384                    // 128 rows x 128B
#define STAGE_B  (2 * TILE_B)             // A | B
#define GEMM_SMEM (STAGES * STAGE_B)      // 96 KB
#define OFF_A 0
#define OFF_B TILE_B

template<bool SPLIT>
__global__ __launch_bounds__(128, 2) void gemm_hmma(
    const __half* __restrict__ Ah,
    const __half* __restrict__ Bh,
    const float* __restrict__ bias, float* __restrict__ C,
    __half* __restrict__ Ch,
    int M, int N, int K)
{
    extern __shared__ char smc[];
    const uint32_t sb = smem_u32(smc);
    const int tid  = threadIdx.x;
    const int warp = tid >> 5, lane = tid & 31;
    const int wm = warp >> 1, wn = warp & 1;      // 2x2 warp grid, 64x64 tiles
    const int bm = blockIdx.y, bn = blockIdx.x;
    const int NC = K / GM_BK;                     // 32

    const __half* gA = Ah + (size_t)bm * 128 * K;
    const __half* gB = Bh + (size_t)bn * 128 * K;

    const int r0 = tid >> 3, c0 = tid & 7;        // 16 rows per pass, 8 chunks

    auto load_stage = [&](int chunk, int slot) {
        const int k0 = chunk * GM_BK;
        uint32_t base = sb + slot * STAGE_B;
        #pragma unroll
        for (int i = 0; i < 8; i++) {
            int r = r0 + i * 16;
            uint32_t so = gsw(r, c0);
            size_t go = (size_t)r * K + k0 + c0 * 8;
            cp_async16(base + OFF_A + so, gA + go);
            cp_async16(base + OFF_B + so, gB + go);
        }
        CP_COMMIT();
    };

    float acc[4][8][4];
    #pragma unroll
    for (int mt = 0; mt < 4; mt++)
        #pragma unroll
        for (int nt = 0; nt < 8; nt++)
            #pragma unroll
            for (int j = 0; j < 4; j++) acc[mt][nt][j] = 0.f;

    const int a_row = wm * 64 + (lane & 15);          // + mt*16
    const int a_cb  = (lane >> 4) & 1;
    const int b_row = wn * 64 + (lane & 7) + ((lane & 16) ? 8 : 0);  // + p*16
    const int b_cb  = (lane >> 3) & 1;

    #pragma unroll
    for (int s = 0; s < STAGES - 1; s++) load_stage(s, s);

    for (int c = 0; c < NC; c++) {
        if (c + STAGES - 1 < NC) { CP_WAIT(STAGES - 2); }
        else                     { CP_WAIT(0); }
        __syncthreads();
        if (c + STAGES - 1 < NC) load_stage(c + STAGES - 1, (c + STAGES - 1) % STAGES);

        const uint32_t base = sb + (c % STAGES) * STAGE_B;

        #pragma unroll
        for (int ks = 0; ks < 4; ks++) {
            uint32_t ahf[4][4];
            #pragma unroll
            for (int mt = 0; mt < 4; mt++)
                ldmx4(ahf[mt], base + OFF_A + gsw(a_row + mt * 16, 2 * ks + a_cb));
            uint32_t bhf[8][2];
            #pragma unroll
            for (int p = 0; p < 4; p++) {
                uint32_t r[4];
                ldmx4(r, base + OFF_B + gsw(b_row + p * 16, 2 * ks + b_cb));
                bhf[2*p][0] = r[0]; bhf[2*p][1] = r[1];
                bhf[2*p+1][0] = r[2]; bhf[2*p+1][1] = r[3];
            }
            #pragma unroll
            for (int mt = 0; mt < 4; mt++)
                #pragma unroll
                for (int nt = 0; nt < 8; nt++)
                    mma_fp16(acc[mt][nt], ahf[mt], bhf[nt]);
        }
    }

    const int erow = bm * 128 + wm * 64 + (lane >> 2);
    const int ecol = bn * 128 + wn * 64 + (lane & 3) * 2;
    #pragma unroll
    for (int mt = 0; mt < 4; mt++)
        #pragma unroll
        for (int nt = 0; nt < 8; nt++) {
            int col = ecol + nt * 8;
            float bx = bias[col], by = bias[col + 1];
            int ra = erow + mt * 16, rb = ra + 8;
            float v0 = acc[mt][nt][0] + bx, v1 = acc[mt][nt][1] + by;
            float v2 = acc[mt][nt][2] + bx, v3 = acc[mt][nt][3] + by;
            if (SPLIT) {
                *(uint32_t*)&Ch[(size_t)ra * N + col] = pack2h(v0, v1);
                *(uint32_t*)&Ch[(size_t)rb * N + col] = pack2h(v2, v3);
            } else {
                float2 o0 = {v0, v1}, o1 = {v2, v3};
                *(float2*)&C[(size_t)ra * N + col] = o0;
                *(float2*)&C[(size_t)rb * N + col] = o1;
            }
        }
}

// ---------------------------------------------------------------------------
// HMMA flash attention. BQ=64, 128 threads (4 warps x 16 q-rows), 2 CTAs/SM:
// one CTA's softmax overlaps the other CTA's MMAs. 80 KB smem/CTA.
// ---------------------------------------------------------------------------
#define AT_BQ 64
#define AT_BK 64
#define AT_NT (SEQ / AT_BK)          // 32
#define AQ_H 0
#define AST(s) (16384 + (s) * 32768)
#define AK_H 0
#define AV_H 16384
#define ATTN_SMEM (16384 + 2 * 32768)   // 80 KB

__global__ __launch_bounds__(128, 2) void attn_hmma(
    const __half* __restrict__ qkv_g,
    __half* __restrict__ oh_g)
{
    extern __shared__ char smc[];
    const uint32_t sb = smem_u32(smc);
    const int tid = threadIdx.x, warp = tid >> 5, lane = tid & 31;
    const int qt = blockIdx.x, bh = blockIdx.y;
    const int b = bh >> 4, h = bh & 15;
    const size_t tok0  = (size_t)b * SEQ + qt * AT_BQ;
    const size_t ktok0 = (size_t)b * SEQ;
    const int colQ = h * 3 * DK, colK = colQ + DK, colV = colQ + 2 * DK;
    const float SCALE = 0.08838834764831845f;

    auto loadQ = [&]() {
        #pragma unroll
        for (int i = 0; i < 8; i++) {
            int idx = tid + i * 128;
            int r = idx >> 4, ch = idx & 15;
            size_t g = (tok0 + r) * QKV_N + colQ + ch * 8;
            cp_async16(sb + AQ_H + asw(r, ch), qkv_g + g);
        }
        CP_COMMIT();
    };
    auto loadK = [&](int kt, int s) {
        #pragma unroll
        for (int i = 0; i < 8; i++) {
            int idx = tid + i * 128;
            int r = idx >> 4, ch = idx & 15;
            size_t g = (ktok0 + kt * AT_BK + r) * QKV_N + colK + ch * 8;
            cp_async16(sb + AST(s) + AK_H + asw(r, ch), qkv_g + g);
        }
        CP_COMMIT();
    };
    auto loadV = [&](int kt, int s) {
        #pragma unroll
        for (int i = 0; i < 8; i++) {
            int idx = tid + i * 128;
            int r = idx >> 4, ch = idx & 15;
            size_t g = (ktok0 + kt * AT_BK + r) * QKV_N + colV + ch * 8;
            cp_async16(sb + AST(s) + AV_H + asw(r, ch), qkv_g + g);
        }
        CP_COMMIT();
    };

    const int aq_row = warp * 16 + (lane & 15);
    const int a_cb   = lane >> 4;
    const int bk_row = (lane & 7) + ((lane & 16) ? 8 : 0);
    const int bk_cb  = (lane >> 3) & 1;
    const int v_row  = (lane & 7) + (((lane >> 3) & 1) << 3);
    const int v_cb   = lane >> 4;

    float oacc[16][4];
    #pragma unroll
    for (int n = 0; n < 16; n++)
        #pragma unroll
        for (int j = 0; j < 4; j++) oacc[n][j] = 0.f;
    float m0 = -1e30f, m1 = -1e30f, l0 = 0.f, l1 = 0.f;

    // prologue: Q, K0, V0, K1
    loadQ();
    loadK(0, 0);
    loadV(0, 0);
    loadK(1, 1);

    // hoist Q fragments into registers
    CP_WAIT(3);
    __syncthreads();
    uint32_t qfh[8][4];
    #pragma unroll
    for (int ks = 0; ks < 8; ks++)
        ldmx4(qfh[ks], sb + AQ_H + asw(aq_row, 2 * ks + a_cb));

    for (int kt = 0; kt < AT_NT; kt++) {
        const int cur = kt & 1;

        CP_WAIT(2);              // K_kt complete
        __syncthreads();
        loadV((kt + 1) % AT_NT, cur ^ 1);   // wrap-around keeps counts exact

        const uint32_t kb = sb + AST(cur);

        // ---- S = Q K^T ----
        float sacc[8][4];
        #pragma unroll
        for (int n = 0; n < 8; n++)
            #pragma unroll
            for (int j = 0; j < 4; j++) sacc[n][j] = 0.f;

        #pragma unroll
        for (int ks = 0; ks < 8; ks++) {
            #pragma unroll
            for (int p = 0; p < 4; p++) {
                uint32_t kh4[4];
                ldmx4(kh4, kb + AK_H + asw(p * 16 + bk_row, 2 * ks + bk_cb));
                mma_fp16(sacc[2*p],   qfh[ks], kh4);
                mma_fp16(sacc[2*p+1], qfh[ks], kh4 + 2);
            }
        }

        // ---- online softmax ----
        float mx0 = -1e30f, mx1 = -1e30f;
        #pragma unroll
        for (int n = 0; n < 8; n++) {
            sacc[n][0] *= SCALE; sacc[n][1] *= SCALE;
            sacc[n][2] *= SCALE; sacc[n][3] *= SCALE;
            mx0 = fmaxf(mx0, fmaxf(sacc[n][0], sacc[n][1]));
            mx1 = fmaxf(mx1, fmaxf(sacc[n][2], sacc[n][3]));
        }
        mx0 = fmaxf(mx0, __shfl_xor_sync(0xffffffffu, mx0, 1));
        mx0 = fmaxf(mx0, __shfl_xor_sync(0xffffffffu, mx0, 2));
        mx1 = fmaxf(mx1, __shfl_xor_sync(0xffffffffu, mx1, 1));
        mx1 = fmaxf(mx1, __shfl_xor_sync(0xffffffffu, mx1, 2));
        const float mn0 = fmaxf(m0, mx0), mn1 = fmaxf(m1, mx1);

        float sum0 = 0.f, sum1 = 0.f;
        uint32_t ph[8][2];
        #pragma unroll
        for (int n = 0; n < 8; n++) {
            float p00 = __expf(sacc[n][0] - mn0), p01 = __expf(sacc[n][1] - mn0);
            float p10 = __expf(sacc[n][2] - mn1), p11 = __expf(sacc[n][3] - mn1);
            sum0 += p00 + p01;
            sum1 += p10 + p11;
            ph[n][0] = pack2h(p00, p01);
            ph[n][1] = pack2h(p10, p11);
        }
        sum0 += __shfl_xor_sync(0xffffffffu, sum0, 1);
        sum0 += __shfl_xor_sync(0xffffffffu, sum0, 2);
        sum1 += __shfl_xor_sync(0xffffffffu, sum1, 1);
        sum1 += __shfl_xor_sync(0xffffffffu, sum1, 2);

        const float al0 = __expf(m0 - mn0), al1 = __expf(m1 - mn1);
        m0 = mn0; m1 = mn1;
        l0 = l0 * al0 + sum0;
        l1 = l1 * al1 + sum1;
        #pragma unroll
        for (int n = 0; n < 16; n++) {
            oacc[n][0] *= al0; oacc[n][1] *= al0;
            oacc[n][2] *= al1; oacc[n][3] *= al1;
        }

        CP_WAIT(2);              // V_kt complete
        __syncthreads();
        loadK((kt + 2) % AT_NT, cur);

        const uint32_t vb = sb + AST(cur);

        // ---- O += P V ----
        #pragma unroll
        for (int kk = 0; kk < 4; kk++) {
            uint32_t pah[4] = {ph[2*kk][0], ph[2*kk][1], ph[2*kk+1][0], ph[2*kk+1][1]};
            #pragma unroll
            for (int p = 0; p < 8; p++) {
                uint32_t vh4[4];
                ldmx4t(vh4, vb + AV_H + asw(kk * 16 + v_row, 2 * p + v_cb));
                mma_fp16(oacc[2*p],   pah, vh4);
                mma_fp16(oacc[2*p+1], pah, vh4 + 2);
            }
        }
    }

    // ---- epilogue: normalize, write fp16 ----
    const float inv0 = 1.f / l0, inv1 = 1.f / l1;
    const int rr = lane >> 2, c2 = (lane & 3) * 2;
    const size_t row0 = tok0 + warp * 16 + rr, row1 = row0 + 8;
    #pragma unroll
    for (int n = 0; n < 16; n++) {
        int col = h * DK + n * 8 + c2;
        *(uint32_t*)&oh_g[row0 * D_MODEL + col] = pack2h(oacc[n][0] * inv0, oacc[n][1] * inv0);
        *(uint32_t*)&oh_g[row1 * D_MODEL + col] = pack2h(oacc[n][2] * inv1, oacc[n][3] * inv1);
    }
}

// ---------------------------------------------------------------------------
extern "C" void kernel_launch(void* const* d_in, const int* in_sizes, int n_in,
                              void* d_out, int out_size)
{
    const float* x    = (const float*)d_in[0];
    const float* Wqkv = (const float*)d_in[1];
    const float* bqkv = (const float*)d_in[2];
    const float* Wout = (const float*)d_in[3];
    const float* bout = (const float*)d_in[4];
    float* out = (float*)d_out;

    __half *qkh, *ah, *wqh, *woh;
    cudaGetSymbolAddress((void**)&qkh, g_qkv_hi);
    cudaGetSymbolAddress((void**)&ah, g_a_hi);
    cudaGetSymbolAddress((void**)&wqh, g_wq_h);
    cudaGetSymbolAddress((void**)&woh, g_wo_h);

    cudaFuncSetAttribute((const void*)gemm_hmma<true>,
                         cudaFuncAttributeMaxDynamicSharedMemorySize, GEMM_SMEM);
    cudaFuncSetAttribute((const void*)gemm_hmma<false>,
                         cudaFuncAttributeMaxDynamicSharedMemorySize, GEMM_SMEM);
    cudaFuncSetAttribute(attn_hmma, cudaFuncAttributeMaxDynamicSharedMemorySize, ATTN_SMEM);

    {
        int n4 = ROWS * D_MODEL / 4;
        convert_half_kernel<<<(n4 + 255) / 256, 256>>>(x, ah, n4);
        transpose_half_kernel<<<dim3(QKV_N / 32, D_MODEL / 32), dim3(32, 8)>>>(
            Wqkv, wqh, D_MODEL, QKV_N);
        transpose_half_kernel<<<dim3(D_MODEL / 32, D_MODEL / 32), dim3(32, 8)>>>(
            Wout, woh, D_MODEL, D_MODEL);
    }

    // 1) QKV projection: fp16 output
    gemm_hmma<true><<<dim3(QKV_N / 128, ROWS / 128), 128, GEMM_SMEM>>>(
        ah, wqh, bqkv, nullptr, qkh, ROWS, QKV_N, D_MODEL);

    // 2) attention -> attn-out fp16 (BQ=64, 2 CTAs/SM)
    attn_hmma<<<dim3(SEQ / AT_BQ, BATCH * NHEADS), 128, ATTN_SMEM>>>(qkh, ah);

    // 3) out-projection: fp32 output
    gemm_hmma<false><<<dim3(D_MODEL / 128, ROWS / 128), 128, GEMM_SMEM>>>(
        ah, woh, bout, out, nullptr, ROWS, D_MODEL, D_MODEL);
}

// round 14
// speedup vs baseline: 1.3201x; 1.3201x over previous
#include <cuda_runtime.h>
#include <cuda_fp16.h>
#include <math.h>
#include <cstdint>

#define D_MODEL 2048
#define NHEADS  16
#define DK      128
#define BATCH   2
#define SEQ     2048
#define ROWS    (BATCH * SEQ)     // 4096
#define QKV_N   (3 * D_MODEL)     // 6144

// ---------------------------------------------------------------------------
// Scratch (device globals — no cudaMalloc allowed)
// ---------------------------------------------------------------------------
__device__ __half g_qkv_hi[ROWS * QKV_N];        // QKV (fp16)
__device__ __half g_a_hi[ROWS * D_MODEL];        // x fp16, then attn-out fp16
__device__ __half g_wq_h[QKV_N * D_MODEL];       // W_qkv^T fp16
__device__ __half g_wo_h[D_MODEL * D_MODEL];     // W_out^T fp16

// ---------------------------------------------------------------------------
// Base-target PTX helpers (virtual target is compute_103 — no tcgen05)
// ---------------------------------------------------------------------------
__device__ __forceinline__ uint32_t smem_u32(const void* p) {
    uint32_t a;
    asm("{ .reg .u64 t; cvta.to.shared.u64 t, %1; cvt.u32.u64 %0, t; }" : "=r"(a) : "l"(p));
    return a;
}
__device__ __forceinline__ void cp_async16(uint32_t saddr, const void* gaddr) {
    asm volatile("cp.async.cg.shared.global [%0], [%1], 16;" :: "r"(saddr), "l"(gaddr));
}
#define CP_COMMIT() asm volatile("cp.async.commit_group;" ::: "memory")
#define CP_WAIT(N)  asm volatile("cp.async.wait_group %0;" :: "n"(N) : "memory")

__device__ __forceinline__ void ldmx4(uint32_t* r, uint32_t addr) {
    asm volatile("ldmatrix.sync.aligned.m8n8.x4.shared.b16 {%0,%1,%2,%3}, [%4];"
                 : "=r"(r[0]), "=r"(r[1]), "=r"(r[2]), "=r"(r[3]) : "r"(addr));
}
__device__ __forceinline__ void ldmx4t(uint32_t* r, uint32_t addr) {
    asm volatile("ldmatrix.sync.aligned.m8n8.x4.trans.shared.b16 {%0,%1,%2,%3}, [%4];"
                 : "=r"(r[0]), "=r"(r[1]), "=r"(r[2]), "=r"(r[3]) : "r"(addr));
}
__device__ __forceinline__ void mma_fp16(float* d, const uint32_t* a, const uint32_t* b) {
    asm volatile(
        "mma.sync.aligned.m16n8k16.row.col.f32.f16.f16.f32 "
        "{%0,%1,%2,%3}, {%4,%5,%6,%7}, {%8,%9}, {%0,%1,%2,%3};"
        : "+f"(d[0]), "+f"(d[1]), "+f"(d[2]), "+f"(d[3])
        : "r"(a[0]), "r"(a[1]), "r"(a[2]), "r"(a[3]), "r"(b[0]), "r"(b[1]));
}

__device__ __forceinline__ uint32_t pack2h(float x, float y) {
    __half2 hh = __halves2half2(__float2half(x), __float2half(y));
    return *(uint32_t*)&hh;
}

// 128B-row smem tile swizzle (8 x 16B chunks per row): chunk ^= row&7
__device__ __forceinline__ uint32_t gsw(int r, int c) {
    return (uint32_t)(r * 128 + ((c ^ (r & 7)) << 4));
}
// Attention smem tile: rows of 128 fp16 (256B = 16 x 16B chunks): chunk ^= row&7
__device__ __forceinline__ uint32_t asw(int row, int ch) {
    return (uint32_t)(row * 256 + ((ch ^ (row & 7)) << 4));
}

// ---------------------------------------------------------------------------
// fp32 -> fp16 convert
__global__ void convert_half_kernel(const float* __restrict__ in,
                                    __half* __restrict__ hi, int n4)
{
    int i = blockIdx.x * blockDim.x + threadIdx.x;
    if (i >= n4) return;
    float4 v = ((const float4*)in)[i];
    ((uint32_t*)hi)[2*i]   = pack2h(v.x, v.y);
    ((uint32_t*)hi)[2*i+1] = pack2h(v.z, v.w);
}

// W[K,N] fp32 -> Wt[N,K] fp16
__global__ void transpose_half_kernel(const float* __restrict__ W,
                                      __half* __restrict__ Th,
                                      int K, int N)
{
    __shared__ float t[32][33];
    int k0 = blockIdx.y * 32, n0 = blockIdx.x * 32;
    #pragma unroll
    for (int i = threadIdx.y; i < 32; i += 8)
        t[i][threadIdx.x] = W[(size_t)(k0 + i) * N + n0 + threadIdx.x];
    __syncthreads();
    #pragma unroll
    for (int i = threadIdx.y; i < 32; i += 8)
        Th[(size_t)(n0 + i) * K + k0 + threadIdx.x] = __float2half(t[threadIdx.x][i]);
}

// ---------------------------------------------------------------------------
// HMMA GEMM: C[M,N] = A[M,K] @ Bt[N,K]^T + bias   (fp16 x fp16, fp32 acc)
// Attention-proven shape: ONE 256-thread CTA per SM, 8 warps (2x4),
// CTA tile 128x256, warp tile 64x64, BK=64, 3-stage pipeline (144 KB smem).
// ---------------------------------------------------------------------------
#define GM_BK    64
#define STAGES   3
#define TILE_A_B 16384                    // 128 rows x 128B
#define TILE_B_B 32768                    // 256 rows x 128B
#define STAGE_B  (TILE_A_B + TILE_B_B)    // 48 KB
#define GEMM_SMEM (STAGES * STAGE_B)      // 144 KB
#define OFF_A 0
#define OFF_B TILE_A_B

template<bool SPLIT>
__global__ __launch_bounds__(256, 1) void gemm_hmma(
    const __half* __restrict__ Ah,
    const __half* __restrict__ Bh,
    const float* __restrict__ bias, float* __restrict__ C,
    __half* __restrict__ Ch,
    int M, int N, int K)
{
    extern __shared__ char smc[];
    const uint32_t sb = smem_u32(smc);
    const int tid  = threadIdx.x;
    const int warp = tid >> 5, lane = tid & 31;
    const int wm = warp >> 2, wn = warp & 3;      // 2x4 warp grid, 64x64 tiles
    const int bm = blockIdx.y, bn = blockIdx.x;
    const int NC = K / GM_BK;                     // 32

    const __half* gA = Ah + (size_t)bm * 128 * K;
    const __half* gB = Bh + (size_t)bn * 256 * K;

    const int r0 = tid >> 3, c0 = tid & 7;        // 32 rows per pass, 8 chunks

    auto load_stage = [&](int chunk, int slot) {
        const int k0 = chunk * GM_BK;
        uint32_t base = sb + slot * STAGE_B;
        #pragma unroll
        for (int i = 0; i < 4; i++) {             // A: 128 rows
            int r = r0 + i * 32;
            cp_async16(base + OFF_A + gsw(r, c0), gA + (size_t)r * K + k0 + c0 * 8);
        }
        #pragma unroll
        for (int i = 0; i < 8; i++) {             // B: 256 rows
            int r = r0 + i * 32;
            cp_async16(base + OFF_B + gsw(r, c0), gB + (size_t)r * K + k0 + c0 * 8);
        }
        CP_COMMIT();
    };

    float acc[4][8][4];
    #pragma unroll
    for (int mt = 0; mt < 4; mt++)
        #pragma unroll
        for (int nt = 0; nt < 8; nt++)
            #pragma unroll
            for (int j = 0; j < 4; j++) acc[mt][nt][j] = 0.f;

    const int a_row = wm * 64 + (lane & 15);          // + mt*16
    const int a_cb  = (lane >> 4) & 1;
    const int b_row = wn * 64 + (lane & 7) + ((lane & 16) ? 8 : 0);  // + p*16
    const int b_cb  = (lane >> 3) & 1;

    #pragma unroll
    for (int s = 0; s < STAGES - 1; s++) load_stage(s, s);

    for (int c = 0; c < NC; c++) {
        if (c + STAGES - 1 < NC) { CP_WAIT(STAGES - 2); }
        else                     { CP_WAIT(0); }
        __syncthreads();
        if (c + STAGES - 1 < NC) load_stage(c + STAGES - 1, (c + STAGES - 1) % STAGES);

        const uint32_t base = sb + (c % STAGES) * STAGE_B;

        #pragma unroll
        for (int ks = 0; ks < 4; ks++) {
            uint32_t ahf[4][4];
            #pragma unroll
            for (int mt = 0; mt < 4; mt++)
                ldmx4(ahf[mt], base + OFF_A + gsw(a_row + mt * 16, 2 * ks + a_cb));
            uint32_t bhf[8][2];
            #pragma unroll
            for (int p = 0; p < 4; p++) {
                uint32_t r[4];
                ldmx4(r, base + OFF_B + gsw(b_row + p * 16, 2 * ks + b_cb));
                bhf[2*p][0] = r[0]; bhf[2*p][1] = r[1];
                bhf[2*p+1][0] = r[2]; bhf[2*p+1][1] = r[3];
            }
            #pragma unroll
            for (int mt = 0; mt < 4; mt++)
                #pragma unroll
                for (int nt = 0; nt < 8; nt++)
                    mma_fp16(acc[mt][nt], ahf[mt], bhf[nt]);
        }
    }

    const int erow = bm * 128 + wm * 64 + (lane >> 2);
    const int ecol = bn * 256 + wn * 64 + (lane & 3) * 2;
    #pragma unroll
    for (int mt = 0; mt < 4; mt++)
        #pragma unroll
        for (int nt = 0; nt < 8; nt++) {
            int col = ecol + nt * 8;
            float bx = bias[col], by = bias[col + 1];
            int ra = erow + mt * 16, rb = ra + 8;
            float v0 = acc[mt][nt][0] + bx, v1 = acc[mt][nt][1] + by;
            float v2 = acc[mt][nt][2] + bx, v3 = acc[mt][nt][3] + by;
            if (SPLIT) {
                *(uint32_t*)&Ch[(size_t)ra * N + col] = pack2h(v0, v1);
                *(uint32_t*)&Ch[(size_t)rb * N + col] = pack2h(v2, v3);
            } else {
                float2 o0 = {v0, v1}, o1 = {v2, v3};
                *(float2*)&C[(size_t)ra * N + col] = o0;
                *(float2*)&C[(size_t)rb * N + col] = o1;
            }
        }
}

// ---------------------------------------------------------------------------
// HMMA flash attention — R12 configuration verbatim (measured 17.7k MMA/us):
// 256 threads, BQ=128, 64-key tiles, double buffer, 96 KB smem, 1 CTA/SM.
// ---------------------------------------------------------------------------
#define AT_BQ 128
#define AT_BK 64
#define AT_NT (SEQ / AT_BK)          // 32
#define AQ_H 0
#define AST(s) (32768 + (s) * 32768)
#define AK_H 0
#define AV_H 16384
#define ATTN_SMEM (32768 + 2 * 32768)   // 96 KB

__global__ __launch_bounds__(256, 1) void attn_hmma(
    const __half* __restrict__ qkv_g,
    __half* __restrict__ oh_g)
{
    extern __shared__ char smc[];
    const uint32_t sb = smem_u32(smc);
    const int tid = threadIdx.x, warp = tid >> 5, lane = tid & 31;
    const int qt = blockIdx.x, bh = blockIdx.y;
    const int b = bh >> 4, h = bh & 15;
    const size_t tok0  = (size_t)b * SEQ + qt * AT_BQ;
    const size_t ktok0 = (size_t)b * SEQ;
    const int colQ = h * 3 * DK, colK = colQ + DK, colV = colQ + 2 * DK;
    const float SCALE = 0.08838834764831845f;

    auto loadQ = [&]() {
        #pragma unroll
        for (int i = 0; i < 8; i++) {
            int idx = tid + i * 256;
            int r = idx >> 4, ch = idx & 15;
            size_t g = (tok0 + r) * QKV_N + colQ + ch * 8;
            cp_async16(sb + AQ_H + asw(r, ch), qkv_g + g);
        }
        CP_COMMIT();
    };
    auto loadK = [&](int kt, int s) {
        #pragma unroll
        for (int i = 0; i < 4; i++) {
            int idx = tid + i * 256;
            int r = idx >> 4, ch = idx & 15;
            size_t g = (ktok0 + kt * AT_BK + r) * QKV_N + colK + ch * 8;
            cp_async16(sb + AST(s) + AK_H + asw(r, ch), qkv_g + g);
        }
        CP_COMMIT();
    };
    auto loadV = [&](int kt, int s) {
        #pragma unroll
        for (int i = 0; i < 4; i++) {
            int idx = tid + i * 256;
            int r = idx >> 4, ch = idx & 15;
            size_t g = (ktok0 + kt * AT_BK + r) * QKV_N + colV + ch * 8;
            cp_async16(sb + AST(s) + AV_H + asw(r, ch), qkv_g + g);
        }
        CP_COMMIT();
    };

    const int aq_row = warp * 16 + (lane & 15);
    const int a_cb   = lane >> 4;
    const int bk_row = (lane & 7) + ((lane & 16) ? 8 : 0);
    const int bk_cb  = (lane >> 3) & 1;
    const int v_row  = (lane & 7) + (((lane >> 3) & 1) << 3);
    const int v_cb   = lane >> 4;

    float oacc[16][4];
    #pragma unroll
    for (int n = 0; n < 16; n++)
        #pragma unroll
        for (int j = 0; j < 4; j++) oacc[n][j] = 0.f;
    float m0 = -1e30f, m1 = -1e30f, l0 = 0.f, l1 = 0.f;

    // prologue: Q, K0, V0, K1
    loadQ();
    loadK(0, 0);
    loadV(0, 0);
    loadK(1, 1);

    // hoist Q fragments into registers
    CP_WAIT(3);
    __syncthreads();
    uint32_t qfh[8][4];
    #pragma unroll
    for (int ks = 0; ks < 8; ks++)
        ldmx4(qfh[ks], sb + AQ_H + asw(aq_row, 2 * ks + a_cb));

    for (int kt = 0; kt < AT_NT; kt++) {
        const int cur = kt & 1;

        CP_WAIT(2);              // K_kt complete
        __syncthreads();
        loadV((kt + 1) % AT_NT, cur ^ 1);   // wrap-around keeps counts exact

        const uint32_t kb = sb + AST(cur);

        // ---- S = Q K^T ----
        float sacc[8][4];
        #pragma unroll
        for (int n = 0; n < 8; n++)
            #pragma unroll
            for (int j = 0; j < 4; j++) sacc[n][j] = 0.f;

        #pragma unroll
        for (int ks = 0; ks < 8; ks++) {
            #pragma unroll
            for (int p = 0; p < 4; p++) {
                uint32_t kh4[4];
                ldmx4(kh4, kb + AK_H + asw(p * 16 + bk_row, 2 * ks + bk_cb));
                mma_fp16(sacc[2*p],   qfh[ks], kh4);
                mma_fp16(sacc[2*p+1], qfh[ks], kh4 + 2);
            }
        }

        // ---- online softmax ----
        float mx0 = -1e30f, mx1 = -1e30f;
        #pragma unroll
        for (int n = 0; n < 8; n++) {
            sacc[n][0] *= SCALE; sacc[n][1] *= SCALE;
            sacc[n][2] *= SCALE; sacc[n][3] *= SCALE;
            mx0 = fmaxf(mx0, fmaxf(sacc[n][0], sacc[n][1]));
            mx1 = fmaxf(mx1, fmaxf(sacc[n][2], sacc[n][3]));
        }
        mx0 = fmaxf(mx0, __shfl_xor_sync(0xffffffffu, mx0, 1));
        mx0 = fmaxf(mx0, __shfl_xor_sync(0xffffffffu, mx0, 2));
        mx1 = fmaxf(mx1, __shfl_xor_sync(0xffffffffu, mx1, 1));
        mx1 = fmaxf(mx1, __shfl_xor_sync(0xffffffffu, mx1, 2));
        const float mn0 = fmaxf(m0, mx0), mn1 = fmaxf(m1, mx1);

        float sum0 = 0.f, sum1 = 0.f;
        uint32_t ph[8][2];
        #pragma unroll
        for (int n = 0; n < 8; n++) {
            float p00 = __expf(sacc[n][0] - mn0), p01 = __expf(sacc[n][1] - mn0);
            float p10 = __expf(sacc[n][2] - mn1), p11 = __expf(sacc[n][3] - mn1);
            sum0 += p00 + p01;
            sum1 += p10 + p11;
            ph[n][0] = pack2h(p00, p01);
            ph[n][1] = pack2h(p10, p11);
        }
        sum0 += __shfl_xor_sync(0xffffffffu, sum0, 1);
        sum0 += __shfl_xor_sync(0xffffffffu, sum0, 2);
        sum1 += __shfl_xor_sync(0xffffffffu, sum1, 1);
        sum1 += __shfl_xor_sync(0xffffffffu, sum1, 2);

        const float al0 = __expf(m0 - mn0), al1 = __expf(m1 - mn1);
        m0 = mn0; m1 = mn1;
        l0 = l0 * al0 + sum0;
        l1 = l1 * al1 + sum1;
        #pragma unroll
        for (int n = 0; n < 16; n++) {
            oacc[n][0] *= al0; oacc[n][1] *= al0;
            oacc[n][2] *= al1; oacc[n][3] *= al1;
        }

        CP_WAIT(2);              // V_kt complete
        __syncthreads();
        loadK((kt + 2) % AT_NT, cur);

        const uint32_t vb = sb + AST(cur);

        // ---- O += P V ----
        #pragma unroll
        for (int kk = 0; kk < 4; kk++) {
            uint32_t pah[4] = {ph[2*kk][0], ph[2*kk][1], ph[2*kk+1][0], ph[2*kk+1][1]};
            #pragma unroll
            for (int p = 0; p < 8; p++) {
                uint32_t vh4[4];
                ldmx4t(vh4, vb + AV_H + asw(kk * 16 + v_row, 2 * p + v_cb));
                mma_fp16(oacc[2*p],   pah, vh4);
                mma_fp16(oacc[2*p+1], pah, vh4 + 2);
            }
        }
    }

    // ---- epilogue: normalize, write fp16 ----
    const float inv0 = 1.f / l0, inv1 = 1.f / l1;
    const int rr = lane >> 2, c2 = (lane & 3) * 2;
    const size_t row0 = tok0 + warp * 16 + rr, row1 = row0 + 8;
    #pragma unroll
    for (int n = 0; n < 16; n++) {
        int col = h * DK + n * 8 + c2;
        *(uint32_t*)&oh_g[row0 * D_MODEL + col] = pack2h(oacc[n][0] * inv0, oacc[n][1] * inv0);
        *(uint32_t*)&oh_g[row1 * D_MODEL + col] = pack2h(oacc[n][2] * inv1, oacc[n][3] * inv1);
    }
}

// ---------------------------------------------------------------------------
extern "C" void kernel_launch(void* const* d_in, const int* in_sizes, int n_in,
                              void* d_out, int out_size)
{
    const float* x    = (const float*)d_in[0];
    const float* Wqkv = (const float*)d_in[1];
    const float* bqkv = (const float*)d_in[2];
    const float* Wout = (const float*)d_in[3];
    const float* bout = (const float*)d_in[4];
    float* out = (float*)d_out;

    __half *qkh, *ah, *wqh, *woh;
    cudaGetSymbolAddress((void**)&qkh, g_qkv_hi);
    cudaGetSymbolAddress((void**)&ah, g_a_hi);
    cudaGetSymbolAddress((void**)&wqh, g_wq_h);
    cudaGetSymbolAddress((void**)&woh, g_wo_h);

    cudaFuncSetAttribute((const void*)gemm_hmma<true>,
                         cudaFuncAttributeMaxDynamicSharedMemorySize, GEMM_SMEM);
    cudaFuncSetAttribute((const void*)gemm_hmma<false>,
                         cudaFuncAttributeMaxDynamicSharedMemorySize, GEMM_SMEM);
    cudaFuncSetAttribute(attn_hmma, cudaFuncAttributeMaxDynamicSharedMemorySize, ATTN_SMEM);

    {
        int n4 = ROWS * D_MODEL / 4;
        convert_half_kernel<<<(n4 + 255) / 256, 256>>>(x, ah, n4);
        transpose_half_kernel<<<dim3(QKV_N / 32, D_MODEL / 32), dim3(32, 8)>>>(
            Wqkv, wqh, D_MODEL, QKV_N);
        transpose_half_kernel<<<dim3(D_MODEL / 32, D_MODEL / 32), dim3(32, 8)>>>(
            Wout, woh, D_MODEL, D_MODEL);
    }

    // 1) QKV projection: fp16 output (CTA tile 128x256)
    gemm_hmma<true><<<dim3(QKV_N / 256, ROWS / 128), 256, GEMM_SMEM>>>(
        ah, wqh, bqkv, nullptr, qkh, ROWS, QKV_N, D_MODEL);

    // 2) attention -> attn-out fp16 (R12 config)
    attn_hmma<<<dim3(SEQ / AT_BQ, BATCH * NHEADS), 256, ATTN_SMEM>>>(qkh, ah);

    // 3) out-projection: fp32 output
    gemm_hmma<false><<<dim3(D_MODEL / 256, ROWS / 128), 256, GEMM_SMEM>>>(
        ah, woh, bout, out, nullptr, ROWS, D_MODEL, D_MODEL);
}

// round 15
// speedup vs baseline: 1.5035x; 1.1390x over previous
#include <cuda_runtime.h>
#include <cuda_fp16.h>
#include <math.h>
#include <cstdint>

#define D_MODEL 2048
#define NHEADS  16
#define DK      128
#define BATCH   2
#define SEQ     2048
#define ROWS    (BATCH * SEQ)     // 4096
#define QKV_N   (3 * D_MODEL)     // 6144

// ---------------------------------------------------------------------------
// Scratch (device globals — no cudaMalloc allowed)
// ---------------------------------------------------------------------------
__device__ __half g_qkv_hi[ROWS * QKV_N];        // QKV (fp16)
__device__ __half g_a_hi[ROWS * D_MODEL];        // x fp16, then attn-out fp16
__device__ __half g_wq_h[QKV_N * D_MODEL];       // W_qkv^T fp16
__device__ __half g_wo_h[D_MODEL * D_MODEL];     // W_out^T fp16

// ---------------------------------------------------------------------------
// Base-target PTX helpers (virtual target is compute_103 — no tcgen05)
// ---------------------------------------------------------------------------
__device__ __forceinline__ uint32_t smem_u32(const void* p) {
    uint32_t a;
    asm("{ .reg .u64 t; cvta.to.shared.u64 t, %1; cvt.u32.u64 %0, t; }" : "=r"(a) : "l"(p));
    return a;
}
__device__ __forceinline__ void cp_async16(uint32_t saddr, const void* gaddr) {
    asm volatile("cp.async.cg.shared.global [%0], [%1], 16;" :: "r"(saddr), "l"(gaddr));
}
#define CP_COMMIT() asm volatile("cp.async.commit_group;" ::: "memory")
#define CP_WAIT(N)  asm volatile("cp.async.wait_group %0;" :: "n"(N) : "memory")

__device__ __forceinline__ void ldmx4(uint32_t* r, uint32_t addr) {
    asm volatile("ldmatrix.sync.aligned.m8n8.x4.shared.b16 {%0,%1,%2,%3}, [%4];"
                 : "=r"(r[0]), "=r"(r[1]), "=r"(r[2]), "=r"(r[3]) : "r"(addr));
}
__device__ __forceinline__ void ldmx4t(uint32_t* r, uint32_t addr) {
    asm volatile("ldmatrix.sync.aligned.m8n8.x4.trans.shared.b16 {%0,%1,%2,%3}, [%4];"
                 : "=r"(r[0]), "=r"(r[1]), "=r"(r[2]), "=r"(r[3]) : "r"(addr));
}
__device__ __forceinline__ void mma_fp16(float* d, const uint32_t* a, const uint32_t* b) {
    asm volatile(
        "mma.sync.aligned.m16n8k16.row.col.f32.f16.f16.f32 "
        "{%0,%1,%2,%3}, {%4,%5,%6,%7}, {%8,%9}, {%0,%1,%2,%3};"
        : "+f"(d[0]), "+f"(d[1]), "+f"(d[2]), "+f"(d[3])
        : "r"(a[0]), "r"(a[1]), "r"(a[2]), "r"(a[3]), "r"(b[0]), "r"(b[1]));
}

__device__ __forceinline__ uint32_t pack2h(float x, float y) {
    __half2 hh = __halves2half2(__float2half(x), __float2half(y));
    return *(uint32_t*)&hh;
}

// 64B-row GEMM smem tile swizzle (4 x 16B chunks per row): chunk ^= (row>>1)&3
__device__ __forceinline__ uint32_t sw_off(int r, int c) {
    return (uint32_t)(r * 64 + ((c ^ ((r >> 1) & 3)) << 4));
}
// Attention smem tile: rows of 128 fp16 (256B = 16 x 16B chunks): chunk ^= row&7
__device__ __forceinline__ uint32_t asw(int row, int ch) {
    return (uint32_t)(row * 256 + ((ch ^ (row & 7)) << 4));
}

// ---------------------------------------------------------------------------
// fp32 -> fp16 convert
__global__ void convert_half_kernel(const float* __restrict__ in,
                                    __half* __restrict__ hi, int n4)
{
    int i = blockIdx.x * blockDim.x + threadIdx.x;
    if (i >= n4) return;
    float4 v = ((const float4*)in)[i];
    ((uint32_t*)hi)[2*i]   = pack2h(v.x, v.y);
    ((uint32_t*)hi)[2*i+1] = pack2h(v.z, v.w);
}

// W[K,N] fp32 -> Wt[N,K] fp16
__global__ void transpose_half_kernel(const float* __restrict__ W,
                                      __half* __restrict__ Th,
                                      int K, int N)
{
    __shared__ float t[32][33];
    int k0 = blockIdx.y * 32, n0 = blockIdx.x * 32;
    #pragma unroll
    for (int i = threadIdx.y; i < 32; i += 8)
        t[i][threadIdx.x] = W[(size_t)(k0 + i) * N + n0 + threadIdx.x];
    __syncthreads();
    #pragma unroll
    for (int i = threadIdx.y; i < 32; i += 8)
        Th[(size_t)(n0 + i) * K + k0 + threadIdx.x] = __float2half(t[threadIdx.x][i]);
}

// ---------------------------------------------------------------------------
// HMMA GEMM — R12 best-measured configuration, verbatim:
// CTA 128x128, 4 warps (2x2), warp tile 64x64, BK=64, 3-stage, 2 CTAs/SM.
// (128B-row swizzle via gsw)
// ---------------------------------------------------------------------------
__device__ __forceinline__ uint32_t gsw(int r, int c) {
    return (uint32_t)(r * 128 + ((c ^ (r & 7)) << 4));
}

#define GM_BK    64
#define STAGES   3
#define TILE_B   16384                    // 128 rows x 128B
#define STAGE_B  (2 * TILE_B)             // A | B
#define GEMM_SMEM (STAGES * STAGE_B)      // 96 KB
#define OFF_A 0
#define OFF_B TILE_B

template<bool SPLIT>
__global__ __launch_bounds__(128, 2) void gemm_hmma(
    const __half* __restrict__ Ah,
    const __half* __restrict__ Bh,
    const float* __restrict__ bias, float* __restrict__ C,
    __half* __restrict__ Ch,
    int M, int N, int K)
{
    extern __shared__ char smc[];
    const uint32_t sb = smem_u32(smc);
    const int tid  = threadIdx.x;
    const int warp = tid >> 5, lane = tid & 31;
    const int wm = warp >> 1, wn = warp & 1;      // 2x2 warp grid, 64x64 tiles
    const int bm = blockIdx.y, bn = blockIdx.x;
    const int NC = K / GM_BK;                     // 32

    const __half* gA = Ah + (size_t)bm * 128 * K;
    const __half* gB = Bh + (size_t)bn * 128 * K;

    const int r0 = tid >> 3, c0 = tid & 7;        // 16 rows per pass, 8 chunks

    auto load_stage = [&](int chunk, int slot) {
        const int k0 = chunk * GM_BK;
        uint32_t base = sb + slot * STAGE_B;
        #pragma unroll
        for (int i = 0; i < 8; i++) {
            int r = r0 + i * 16;
            uint32_t so = gsw(r, c0);
            size_t go = (size_t)r * K + k0 + c0 * 8;
            cp_async16(base + OFF_A + so, gA + go);
            cp_async16(base + OFF_B + so, gB + go);
        }
        CP_COMMIT();
    };

    float acc[4][8][4];
    #pragma unroll
    for (int mt = 0; mt < 4; mt++)
        #pragma unroll
        for (int nt = 0; nt < 8; nt++)
            #pragma unroll
            for (int j = 0; j < 4; j++) acc[mt][nt][j] = 0.f;

    const int a_row = wm * 64 + (lane & 15);          // + mt*16
    const int a_cb  = (lane >> 4) & 1;
    const int b_row = wn * 64 + (lane & 7) + ((lane & 16) ? 8 : 0);  // + p*16
    const int b_cb  = (lane >> 3) & 1;

    #pragma unroll
    for (int s = 0; s < STAGES - 1; s++) load_stage(s, s);

    for (int c = 0; c < NC; c++) {
        if (c + STAGES - 1 < NC) { CP_WAIT(STAGES - 2); }
        else                     { CP_WAIT(0); }
        __syncthreads();
        if (c + STAGES - 1 < NC) load_stage(c + STAGES - 1, (c + STAGES - 1) % STAGES);

        const uint32_t base = sb + (c % STAGES) * STAGE_B;

        #pragma unroll
        for (int ks = 0; ks < 4; ks++) {
            uint32_t ahf[4][4];
            #pragma unroll
            for (int mt = 0; mt < 4; mt++)
                ldmx4(ahf[mt], base + OFF_A + gsw(a_row + mt * 16, 2 * ks + a_cb));
            uint32_t bhf[8][2];
            #pragma unroll
            for (int p = 0; p < 4; p++) {
                uint32_t r[4];
                ldmx4(r, base + OFF_B + gsw(b_row + p * 16, 2 * ks + b_cb));
                bhf[2*p][0] = r[0]; bhf[2*p][1] = r[1];
                bhf[2*p+1][0] = r[2]; bhf[2*p+1][1] = r[3];
            }
            #pragma unroll
            for (int mt = 0; mt < 4; mt++)
                #pragma unroll
                for (int nt = 0; nt < 8; nt++)
                    mma_fp16(acc[mt][nt], ahf[mt], bhf[nt]);
        }
    }

    const int erow = bm * 128 + wm * 64 + (lane >> 2);
    const int ecol = bn * 128 + wn * 64 + (lane & 3) * 2;
    #pragma unroll
    for (int mt = 0; mt < 4; mt++)
        #pragma unroll
        for (int nt = 0; nt < 8; nt++) {
            int col = ecol + nt * 8;
            float bx = bias[col], by = bias[col + 1];
            int ra = erow + mt * 16, rb = ra + 8;
            float v0 = acc[mt][nt][0] + bx, v1 = acc[mt][nt][1] + by;
            float v2 = acc[mt][nt][2] + bx, v3 = acc[mt][nt][3] + by;
            if (SPLIT) {
                *(uint32_t*)&Ch[(size_t)ra * N + col] = pack2h(v0, v1);
                *(uint32_t*)&Ch[(size_t)rb * N + col] = pack2h(v2, v3);
            } else {
                float2 o0 = {v0, v1}, o1 = {v2, v3};
                *(float2*)&C[(size_t)ra * N + col] = o0;
                *(float2*)&C[(size_t)rb * N + col] = o1;
            }
        }
}

// ---------------------------------------------------------------------------
// HMMA flash attention: R12 shape (256 thr, BQ=128, 1 CTA/SM) with K-tile
// 64 -> 128: per-tile fixed costs (barriers, waits, shuffles, rescale) halve.
// smem: Q 32K + 2 x (K 32K + V 32K) = 160 KB.
// ---------------------------------------------------------------------------
#define AT_BQ 128
#define AT_BK 128
#define AT_NT (SEQ / AT_BK)          // 16
#define AQ_H 0
#define AST(s) (32768 + (s) * 65536)
#define AK_H 0
#define AV_H 32768
#define ATTN_SMEM (32768 + 2 * 65536)   // 160 KB

__global__ __launch_bounds__(256, 1) void attn_hmma(
    const __half* __restrict__ qkv_g,
    __half* __restrict__ oh_g)
{
    extern __shared__ char smc[];
    const uint32_t sb = smem_u32(smc);
    const int tid = threadIdx.x, warp = tid >> 5, lane = tid & 31;
    const int qt = blockIdx.x, bh = blockIdx.y;
    const int b = bh >> 4, h = bh & 15;
    const size_t tok0  = (size_t)b * SEQ + qt * AT_BQ;
    const size_t ktok0 = (size_t)b * SEQ;
    const int colQ = h * 3 * DK, colK = colQ + DK, colV = colQ + 2 * DK;
    const float SCALE = 0.08838834764831845f;

    auto loadQ = [&]() {
        #pragma unroll
        for (int i = 0; i < 8; i++) {
            int idx = tid + i * 256;
            int r = idx >> 4, ch = idx & 15;
            size_t g = (tok0 + r) * QKV_N + colQ + ch * 8;
            cp_async16(sb + AQ_H + asw(r, ch), qkv_g + g);
        }
        CP_COMMIT();
    };
    auto loadK = [&](int kt, int s) {
        #pragma unroll
        for (int i = 0; i < 8; i++) {
            int idx = tid + i * 256;
            int r = idx >> 4, ch = idx & 15;
            size_t g = (ktok0 + kt * AT_BK + r) * QKV_N + colK + ch * 8;
            cp_async16(sb + AST(s) + AK_H + asw(r, ch), qkv_g + g);
        }
        CP_COMMIT();
    };
    auto loadV = [&](int kt, int s) {
        #pragma unroll
        for (int i = 0; i < 8; i++) {
            int idx = tid + i * 256;
            int r = idx >> 4, ch = idx & 15;
            size_t g = (ktok0 + kt * AT_BK + r) * QKV_N + colV + ch * 8;
            cp_async16(sb + AST(s) + AV_H + asw(r, ch), qkv_g + g);
        }
        CP_COMMIT();
    };

    const int aq_row = warp * 16 + (lane & 15);
    const int a_cb   = lane >> 4;
    const int bk_row = (lane & 7) + ((lane & 16) ? 8 : 0);
    const int bk_cb  = (lane >> 3) & 1;
    const int v_row  = (lane & 7) + (((lane >> 3) & 1) << 3);
    const int v_cb   = lane >> 4;

    float oacc[16][4];
    #pragma unroll
    for (int n = 0; n < 16; n++)
        #pragma unroll
        for (int j = 0; j < 4; j++) oacc[n][j] = 0.f;
    float m0 = -1e30f, m1 = -1e30f, l0 = 0.f, l1 = 0.f;

    // prologue: Q, K0, V0, K1
    loadQ();
    loadK(0, 0);
    loadV(0, 0);
    loadK(1, 1);

    // hoist Q fragments into registers
    CP_WAIT(3);
    __syncthreads();
    uint32_t qfh[8][4];
    #pragma unroll
    for (int ks = 0; ks < 8; ks++)
        ldmx4(qfh[ks], sb + AQ_H + asw(aq_row, 2 * ks + a_cb));

    for (int kt = 0; kt < AT_NT; kt++) {
        const int cur = kt & 1;

        CP_WAIT(2);              // K_kt complete
        __syncthreads();
        loadV((kt + 1) % AT_NT, cur ^ 1);   // wrap-around keeps counts exact

        const uint32_t kb = sb + AST(cur);

        // ---- S = Q K^T  (128 q x 128 keys) ----
        float sacc[16][4];
        #pragma unroll
        for (int n = 0; n < 16; n++)
            #pragma unroll
            for (int j = 0; j < 4; j++) sacc[n][j] = 0.f;

        #pragma unroll
        for (int ks = 0; ks < 8; ks++) {
            #pragma unroll
            for (int p = 0; p < 8; p++) {
                uint32_t kh4[4];
                ldmx4(kh4, kb + AK_H + asw(p * 16 + bk_row, 2 * ks + bk_cb));
                mma_fp16(sacc[2*p],   qfh[ks], kh4);
                mma_fp16(sacc[2*p+1], qfh[ks], kh4 + 2);
            }
        }

        // ---- online softmax ----
        float mx0 = -1e30f, mx1 = -1e30f;
        #pragma unroll
        for (int n = 0; n < 16; n++) {
            sacc[n][0] *= SCALE; sacc[n][1] *= SCALE;
            sacc[n][2] *= SCALE; sacc[n][3] *= SCALE;
            mx0 = fmaxf(mx0, fmaxf(sacc[n][0], sacc[n][1]));
            mx1 = fmaxf(mx1, fmaxf(sacc[n][2], sacc[n][3]));
        }
        mx0 = fmaxf(mx0, __shfl_xor_sync(0xffffffffu, mx0, 1));
        mx0 = fmaxf(mx0, __shfl_xor_sync(0xffffffffu, mx0, 2));
        mx1 = fmaxf(mx1, __shfl_xor_sync(0xffffffffu, mx1, 1));
        mx1 = fmaxf(mx1, __shfl_xor_sync(0xffffffffu, mx1, 2));
        const float mn0 = fmaxf(m0, mx0), mn1 = fmaxf(m1, mx1);

        float sum0 = 0.f, sum1 = 0.f;
        uint32_t ph[16][2];
        #pragma unroll
        for (int n = 0; n < 16; n++) {
            float p00 = __expf(sacc[n][0] - mn0), p01 = __expf(sacc[n][1] - mn0);
            float p10 = __expf(sacc[n][2] - mn1), p11 = __expf(sacc[n][3] - mn1);
            sum0 += p00 + p01;
            sum1 += p10 + p11;
            ph[n][0] = pack2h(p00, p01);
            ph[n][1] = pack2h(p10, p11);
        }
        sum0 += __shfl_xor_sync(0xffffffffu, sum0, 1);
        sum0 += __shfl_xor_sync(0xffffffffu, sum0, 2);
        sum1 += __shfl_xor_sync(0xffffffffu, sum1, 1);
        sum1 += __shfl_xor_sync(0xffffffffu, sum1, 2);

        const float al0 = __expf(m0 - mn0), al1 = __expf(m1 - mn1);
        m0 = mn0; m1 = mn1;
        l0 = l0 * al0 + sum0;
        l1 = l1 * al1 + sum1;
        #pragma unroll
        for (int n = 0; n < 16; n++) {
            oacc[n][0] *= al0; oacc[n][1] *= al0;
            oacc[n][2] *= al1; oacc[n][3] *= al1;
        }

        CP_WAIT(2);              // V_kt complete
        __syncthreads();
        loadK((kt + 2) % AT_NT, cur);

        const uint32_t vb = sb + AST(cur);

        // ---- O += P V  (128 keys) ----
        #pragma unroll
        for (int kk = 0; kk < 8; kk++) {
            uint32_t pah[4] = {ph[2*kk][0], ph[2*kk][1], ph[2*kk+1][0], ph[2*kk+1][1]};
            #pragma unroll
            for (int p = 0; p < 8; p++) {
                uint32_t vh4[4];
                ldmx4t(vh4, vb + AV_H + asw(kk * 16 + v_row, 2 * p + v_cb));
                mma_fp16(oacc[2*p],   pah, vh4);
                mma_fp16(oacc[2*p+1], pah, vh4 + 2);
            }
        }
    }

    // ---- epilogue: normalize, write fp16 ----
    const float inv0 = 1.f / l0, inv1 = 1.f / l1;
    const int rr = lane >> 2, c2 = (lane & 3) * 2;
    const size_t row0 = tok0 + warp * 16 + rr, row1 = row0 + 8;
    #pragma unroll
    for (int n = 0; n < 16; n++) {
        int col = h * DK + n * 8 + c2;
        *(uint32_t*)&oh_g[row0 * D_MODEL + col] = pack2h(oacc[n][0] * inv0, oacc[n][1] * inv0);
        *(uint32_t*)&oh_g[row1 * D_MODEL + col] = pack2h(oacc[n][2] * inv1, oacc[n][3] * inv1);
    }
}

// ---------------------------------------------------------------------------
extern "C" void kernel_launch(void* const* d_in, const int* in_sizes, int n_in,
                              void* d_out, int out_size)
{
    const float* x    = (const float*)d_in[0];
    const float* Wqkv = (const float*)d_in[1];
    const float* bqkv = (const float*)d_in[2];
    const float* Wout = (const float*)d_in[3];
    const float* bout = (const float*)d_in[4];
    float* out = (float*)d_out;

    __half *qkh, *ah, *wqh, *woh;
    cudaGetSymbolAddress((void**)&qkh, g_qkv_hi);
    cudaGetSymbolAddress((void**)&ah, g_a_hi);
    cudaGetSymbolAddress((void**)&wqh, g_wq_h);
    cudaGetSymbolAddress((void**)&woh, g_wo_h);

    cudaFuncSetAttribute((const void*)gemm_hmma<true>,
                         cudaFuncAttributeMaxDynamicSharedMemorySize, GEMM_SMEM);
    cudaFuncSetAttribute((const void*)gemm_hmma<false>,
                         cudaFuncAttributeMaxDynamicSharedMemorySize, GEMM_SMEM);
    cudaFuncSetAttribute(attn_hmma, cudaFuncAttributeMaxDynamicSharedMemorySize, ATTN_SMEM);

    {
        int n4 = ROWS * D_MODEL / 4;
        convert_half_kernel<<<(n4 + 255) / 256, 256>>>(x, ah, n4);
        transpose_half_kernel<<<dim3(QKV_N / 32, D_MODEL / 32), dim3(32, 8)>>>(
            Wqkv, wqh, D_MODEL, QKV_N);
        transpose_half_kernel<<<dim3(D_MODEL / 32, D_MODEL / 32), dim3(32, 8)>>>(
            Wout, woh, D_MODEL, D_MODEL);
    }

    // 1) QKV projection: fp16 output (R12 config)
    gemm_hmma<true><<<dim3(QKV_N / 128, ROWS / 128), 128, GEMM_SMEM>>>(
        ah, wqh, bqkv, nullptr, qkh, ROWS, QKV_N, D_MODEL);

    // 2) attention -> attn-out fp16 (BK=128)
    attn_hmma<<<dim3(SEQ / AT_BQ, BATCH * NHEADS), 256, ATTN_SMEM>>>(qkh, ah);

    // 3) out-projection: fp32 output (R12 config)
    gemm_hmma<false><<<dim3(D_MODEL / 128, ROWS / 128), 128, GEMM_SMEM>>>(
        ah, woh, bout, out, nullptr, ROWS, D_MODEL, D_MODEL);
}

// round 17
// speedup vs baseline: 1.5227x; 1.0128x over previous
#include <cuda_runtime.h>
#include <cuda_fp16.h>
#include <math.h>
#include <cstdint>

#define D_MODEL 2048
#define NHEADS  16
#define DK      128
#define BATCH   2
#define SEQ     2048
#define ROWS    (BATCH * SEQ)     // 4096
#define QKV_N   (3 * D_MODEL)     // 6144

// ---------------------------------------------------------------------------
// Scratch (device globals — no cudaMalloc allowed)
// ---------------------------------------------------------------------------
__device__ __half g_qkv_hi[ROWS * QKV_N];        // QKV (fp16)
__device__ __half g_a_hi[ROWS * D_MODEL];        // x fp16, then attn-out fp16
__device__ __half g_wq_h[QKV_N * D_MODEL];       // W_qkv^T fp16
__device__ __half g_wo_h[D_MODEL * D_MODEL];     // W_out^T fp16

// ---------------------------------------------------------------------------
// Base-target PTX helpers (virtual target is compute_103 — no tcgen05)
// ---------------------------------------------------------------------------
__device__ __forceinline__ uint32_t smem_u32(const void* p) {
    uint32_t a;
    asm("{ .reg .u64 t; cvta.to.shared.u64 t, %1; cvt.u32.u64 %0, t; }" : "=r"(a) : "l"(p));
    return a;
}
__device__ __forceinline__ void cp_async16(uint32_t saddr, const void* gaddr) {
    asm volatile("cp.async.cg.shared.global [%0], [%1], 16;" :: "r"(saddr), "l"(gaddr));
}
#define CP_COMMIT() asm volatile("cp.async.commit_group;" ::: "memory")
#define CP_WAIT(N)  asm volatile("cp.async.wait_group %0;" :: "n"(N) : "memory")

__device__ __forceinline__ void ldmx4(uint32_t* r, uint32_t addr) {
    asm volatile("ldmatrix.sync.aligned.m8n8.x4.shared.b16 {%0,%1,%2,%3}, [%4];"
                 : "=r"(r[0]), "=r"(r[1]), "=r"(r[2]), "=r"(r[3]) : "r"(addr));
}
__device__ __forceinline__ void ldmx4t(uint32_t* r, uint32_t addr) {
    asm volatile("ldmatrix.sync.aligned.m8n8.x4.trans.shared.b16 {%0,%1,%2,%3}, [%4];"
                 : "=r"(r[0]), "=r"(r[1]), "=r"(r[2]), "=r"(r[3]) : "r"(addr));
}
__device__ __forceinline__ void mma_fp16(float* d, const uint32_t* a, const uint32_t* b) {
    asm volatile(
        "mma.sync.aligned.m16n8k16.row.col.f32.f16.f16.f32 "
        "{%0,%1,%2,%3}, {%4,%5,%6,%7}, {%8,%9}, {%0,%1,%2,%3};"
        : "+f"(d[0]), "+f"(d[1]), "+f"(d[2]), "+f"(d[3])
        : "r"(a[0]), "r"(a[1]), "r"(a[2]), "r"(a[3]), "r"(b[0]), "r"(b[1]));
}

__device__ __forceinline__ uint32_t pack2h(float x, float y) {
    __half2 hh = __halves2half2(__float2half(x), __float2half(y));
    return *(uint32_t*)&hh;
}

// 128B-row smem tile swizzle (8 x 16B chunks per row): chunk ^= row&7
__device__ __forceinline__ uint32_t gsw(int r, int c) {
    return (uint32_t)(r * 128 + ((c ^ (r & 7)) << 4));
}
// Attention smem tile: rows of 128 fp16 (256B = 16 x 16B chunks): chunk ^= row&7
__device__ __forceinline__ uint32_t asw(int row, int ch) {
    return (uint32_t)(row * 256 + ((ch ^ (row & 7)) << 4));
}

// ---------------------------------------------------------------------------
// Fused preprocessing: ONE launch, flat grid, three sections.
//   [0, CV_BLK)                : x fp32 -> fp16
//   [CV_BLK, CV_BLK+WQ_BLK)    : W_qkv [K,N] -> W_qkv^T [N,K] fp16
//   [.., +WO_BLK)              : W_out  [K,N] -> W_out^T [N,K] fp16
// All blocks 256 threads (32x8 for transposes, flat for convert).
// ---------------------------------------------------------------------------
#define CV_N4   (ROWS * D_MODEL / 4)          // 2M float4
#define CV_BLK  (CV_N4 / 256)                 // 8192
#define WQ_BX   (QKV_N / 32)                  // 192
#define WQ_BLK  (WQ_BX * (D_MODEL / 32))      // 12288
#define WO_BX   (D_MODEL / 32)                // 64
#define WO_BLK  (WO_BX * (D_MODEL / 32))      // 4096
#define PREP_BLK (CV_BLK + WQ_BLK + WO_BLK)   // 24576

__device__ __forceinline__ void transpose_tile(
    const float* __restrict__ W, __half* __restrict__ Th,
    int K, int N, int bx, int by, int tx, int ty)
{
    __shared__ float t[32][33];
    int k0 = by * 32, n0 = bx * 32;
    #pragma unroll
    for (int i = ty; i < 32; i += 8)
        t[i][tx] = W[(size_t)(k0 + i) * N + n0 + tx];
    __syncthreads();
    #pragma unroll
    for (int i = ty; i < 32; i += 8)
        Th[(size_t)(n0 + i) * K + k0 + tx] = __float2half(t[tx][i]);
}

__global__ void prep_kernel(const float* __restrict__ x, __half* __restrict__ ah,
                            const float* __restrict__ Wqkv, __half* __restrict__ wqh,
                            const float* __restrict__ Wout, __half* __restrict__ woh)
{
    const int bid = blockIdx.x;
    const int tx = threadIdx.x, ty = threadIdx.y;
    const int tid = ty * 32 + tx;

    if (bid < CV_BLK) {
        int i = bid * 256 + tid;
        float4 v = ((const float4*)x)[i];
        ((uint32_t*)ah)[2*i]   = pack2h(v.x, v.y);
        ((uint32_t*)ah)[2*i+1] = pack2h(v.z, v.w);
    } else if (bid < CV_BLK + WQ_BLK) {
        int r = bid - CV_BLK;
        transpose_tile(Wqkv, wqh, D_MODEL, QKV_N, r % WQ_BX, r / WQ_BX, tx, ty);
    } else {
        int r = bid - CV_BLK - WQ_BLK;
        transpose_tile(Wout, woh, D_MODEL, D_MODEL, r % WO_BX, r / WO_BX, tx, ty);
    }
}

// ---------------------------------------------------------------------------
// HMMA GEMM — R12/R15 best-measured configuration, verbatim:
// CTA 128x128, 4 warps (2x2), warp tile 64x64, BK=64, 3-stage, 2 CTAs/SM.
// ---------------------------------------------------------------------------
#define GM_BK    64
#define STAGES   3
#define TILE_B   16384                    // 128 rows x 128B
#define STAGE_B  (2 * TILE_B)             // A | B
#define GEMM_SMEM (STAGES * STAGE_B)      // 96 KB
#define OFF_A 0
#define OFF_B TILE_B

template<bool SPLIT>
__global__ __launch_bounds__(128, 2) void gemm_hmma(
    const __half* __restrict__ Ah,
    const __half* __restrict__ Bh,
    const float* __restrict__ bias, float* __restrict__ C,
    __half* __restrict__ Ch,
    int M, int N, int K)
{
    extern __shared__ char smc[];
    const uint32_t sb = smem_u32(smc);
    const int tid  = threadIdx.x;
    const int warp = tid >> 5, lane = tid & 31;
    const int wm = warp >> 1, wn = warp & 1;      // 2x2 warp grid, 64x64 tiles
    const int bm = blockIdx.y, bn = blockIdx.x;
    const int NC = K / GM_BK;                     // 32

    const __half* gA = Ah + (size_t)bm * 128 * K;
    const __half* gB = Bh + (size_t)bn * 128 * K;

    const int r0 = tid >> 3, c0 = tid & 7;        // 16 rows per pass, 8 chunks

    auto load_stage = [&](int chunk, int slot) {
        const int k0 = chunk * GM_BK;
        uint32_t base = sb + slot * STAGE_B;
        #pragma unroll
        for (int i = 0; i < 8; i++) {
            int r = r0 + i * 16;
            uint32_t so = gsw(r, c0);
            size_t go = (size_t)r * K + k0 + c0 * 8;
            cp_async16(base + OFF_A + so, gA + go);
            cp_async16(base + OFF_B + so, gB + go);
        }
        CP_COMMIT();
    };

    float acc[4][8][4];
    #pragma unroll
    for (int mt = 0; mt < 4; mt++)
        #pragma unroll
        for (int nt = 0; nt < 8; nt++)
            #pragma unroll
            for (int j = 0; j < 4; j++) acc[mt][nt][j] = 0.f;

    const int a_row = wm * 64 + (lane & 15);          // + mt*16
    const int a_cb  = (lane >> 4) & 1;
    const int b_row = wn * 64 + (lane & 7) + ((lane & 16) ? 8 : 0);  // + p*16
    const int b_cb  = (lane >> 3) & 1;

    #pragma unroll
    for (int s = 0; s < STAGES - 1; s++) load_stage(s, s);

    for (int c = 0; c < NC; c++) {
        if (c + STAGES - 1 < NC) { CP_WAIT(STAGES - 2); }
        else                     { CP_WAIT(0); }
        __syncthreads();
        if (c + STAGES - 1 < NC) load_stage(c + STAGES - 1, (c + STAGES - 1) % STAGES);

        const uint32_t base = sb + (c % STAGES) * STAGE_B;

        #pragma unroll
        for (int ks = 0; ks < 4; ks++) {
            uint32_t ahf[4][4];
            #pragma unroll
            for (int mt = 0; mt < 4; mt++)
                ldmx4(ahf[mt], base + OFF_A + gsw(a_row + mt * 16, 2 * ks + a_cb));
            uint32_t bhf[8][2];
            #pragma unroll
            for (int p = 0; p < 4; p++) {
                uint32_t r[4];
                ldmx4(r, base + OFF_B + gsw(b_row + p * 16, 2 * ks + b_cb));
                bhf[2*p][0] = r[0]; bhf[2*p][1] = r[1];
                bhf[2*p+1][0] = r[2]; bhf[2*p+1][1] = r[3];
            }
            #pragma unroll
            for (int mt = 0; mt < 4; mt++)
                #pragma unroll
                for (int nt = 0; nt < 8; nt++)
                    mma_fp16(acc[mt][nt], ahf[mt], bhf[nt]);
        }
    }

    const int erow = bm * 128 + wm * 64 + (lane >> 2);
    const int ecol = bn * 128 + wn * 64 + (lane & 3) * 2;
    #pragma unroll
    for (int mt = 0; mt < 4; mt++)
        #pragma unroll
        for (int nt = 0; nt < 8; nt++) {
            int col = ecol + nt * 8;
            float bx = bias[col], by = bias[col + 1];
            int ra = erow + mt * 16, rb = ra + 8;
            float v0 = acc[mt][nt][0] + bx, v1 = acc[mt][nt][1] + by;
            float v2 = acc[mt][nt][2] + bx, v3 = acc[mt][nt][3] + by;
            if (SPLIT) {
                *(uint32_t*)&Ch[(size_t)ra * N + col] = pack2h(v0, v1);
                *(uint32_t*)&Ch[(size_t)rb * N + col] = pack2h(v2, v3);
            } else {
                float2 o0 = {v0, v1}, o1 = {v2, v3};
                *(float2*)&C[(size_t)ra * N + col] = o0;
                *(float2*)&C[(size_t)rb * N + col] = o1;
            }
        }
}

// ---------------------------------------------------------------------------
// HMMA flash attention — R15 configuration verbatim:
// 256 thr, BQ=128, BK=128, double buffer, 160 KB smem, 1 CTA/SM.
// ---------------------------------------------------------------------------
#define AT_BQ 128
#define AT_BK 128
#define AT_NT (SEQ / AT_BK)          // 16
#define AQ_H 0
#define AST(s) (32768 + (s) * 65536)
#define AK_H 0
#define AV_H 32768
#define ATTN_SMEM (32768 + 2 * 65536)   // 160 KB

__global__ __launch_bounds__(256, 1) void attn_hmma(
    const __half* __restrict__ qkv_g,
    __half* __restrict__ oh_g)
{
    extern __shared__ char smc[];
    const uint32_t sb = smem_u32(smc);
    const int tid = threadIdx.x, warp = tid >> 5, lane = tid & 31;
    const int qt = blockIdx.x, bh = blockIdx.y;
    const int b = bh >> 4, h = bh & 15;
    const size_t tok0  = (size_t)b * SEQ + qt * AT_BQ;
    const size_t ktok0 = (size_t)b * SEQ;
    const int colQ = h * 3 * DK, colK = colQ + DK, colV = colQ + 2 * DK;
    const float SCALE = 0.08838834764831845f;

    auto loadQ = [&]() {
        #pragma unroll
        for (int i = 0; i < 8; i++) {
            int idx = tid + i * 256;
            int r = idx >> 4, ch = idx & 15;
            size_t g = (tok0 + r) * QKV_N + colQ + ch * 8;
            cp_async16(sb + AQ_H + asw(r, ch), qkv_g + g);
        }
        CP_COMMIT();
    };
    auto loadK = [&](int kt, int s) {
        #pragma unroll
        for (int i = 0; i < 8; i++) {
            int idx = tid + i * 256;
            int r = idx >> 4, ch = idx & 15;
            size_t g = (ktok0 + kt * AT_BK + r) * QKV_N + colK + ch * 8;
            cp_async16(sb + AST(s) + AK_H + asw(r, ch), qkv_g + g);
        }
        CP_COMMIT();
    };
    auto loadV = [&](int kt, int s) {
        #pragma unroll
        for (int i = 0; i < 8; i++) {
            int idx = tid + i * 256;
            int r = idx >> 4, ch = idx & 15;
            size_t g = (ktok0 + kt * AT_BK + r) * QKV_N + colV + ch * 8;
            cp_async16(sb + AST(s) + AV_H + asw(r, ch), qkv_g + g);
        }
        CP_COMMIT();
    };

    const int aq_row = warp * 16 + (lane & 15);
    const int a_cb   = lane >> 4;
    const int bk_row = (lane & 7) + ((lane & 16) ? 8 : 0);
    const int bk_cb  = (lane >> 3) & 1;
    const int v_row  = (lane & 7) + (((lane >> 3) & 1) << 3);
    const int v_cb   = lane >> 4;

    float oacc[16][4];
    #pragma unroll
    for (int n = 0; n < 16; n++)
        #pragma unroll
        for (int j = 0; j < 4; j++) oacc[n][j] = 0.f;
    float m0 = -1e30f, m1 = -1e30f, l0 = 0.f, l1 = 0.f;

    // prologue: Q, K0, V0, K1
    loadQ();
    loadK(0, 0);
    loadV(0, 0);
    loadK(1, 1);

    // hoist Q fragments into registers
    CP_WAIT(3);
    __syncthreads();
    uint32_t qfh[8][4];
    #pragma unroll
    for (int ks = 0; ks < 8; ks++)
        ldmx4(qfh[ks], sb + AQ_H + asw(aq_row, 2 * ks + a_cb));

    for (int kt = 0; kt < AT_NT; kt++) {
        const int cur = kt & 1;

        CP_WAIT(2);              // K_kt complete
        __syncthreads();
        loadV((kt + 1) % AT_NT, cur ^ 1);   // wrap-around keeps counts exact

        const uint32_t kb = sb + AST(cur);

        // ---- S = Q K^T  (128 q x 128 keys) ----
        float sacc[16][4];
        #pragma unroll
        for (int n = 0; n < 16; n++)
            #pragma unroll
            for (int j = 0; j < 4; j++) sacc[n][j] = 0.f;

        #pragma unroll
        for (int ks = 0; ks < 8; ks++) {
            #pragma unroll
            for (int p = 0; p < 8; p++) {
                uint32_t kh4[4];
                ldmx4(kh4, kb + AK_H + asw(p * 16 + bk_row, 2 * ks + bk_cb));
                mma_fp16(sacc[2*p],   qfh[ks], kh4);
                mma_fp16(sacc[2*p+1], qfh[ks], kh4 + 2);
            }
        }

        // ---- online softmax ----
        float mx0 = -1e30f, mx1 = -1e30f;
        #pragma unroll
        for (int n = 0; n < 16; n++) {
            sacc[n][0] *= SCALE; sacc[n][1] *= SCALE;
            sacc[n][2] *= SCALE; sacc[n][3] *= SCALE;
            mx0 = fmaxf(mx0, fmaxf(sacc[n][0], sacc[n][1]));
            mx1 = fmaxf(mx1, fmaxf(sacc[n][2], sacc[n][3]));
        }
        mx0 = fmaxf(mx0, __shfl_xor_sync(0xffffffffu, mx0, 1));
        mx0 = fmaxf(mx0, __shfl_xor_sync(0xffffffffu, mx0, 2));
        mx1 = fmaxf(mx1, __shfl_xor_sync(0xffffffffu, mx1, 1));
        mx1 = fmaxf(mx1, __shfl_xor_sync(0xffffffffu, mx1, 2));
        const float mn0 = fmaxf(m0, mx0), mn1 = fmaxf(m1, mx1);

        float sum0 = 0.f, sum1 = 0.f;
        uint32_t ph[16][2];
        #pragma unroll
        for (int n = 0; n < 16; n++) {
            float p00 = __expf(sacc[n][0] - mn0), p01 = __expf(sacc[n][1] - mn0);
            float p10 = __expf(sacc[n][2] - mn1), p11 = __expf(sacc[n][3] - mn1);
            sum0 += p00 + p01;
            sum1 += p10 + p11;
            ph[n][0] = pack2h(p00, p01);
            ph[n][1] = pack2h(p10, p11);
        }
        sum0 += __shfl_xor_sync(0xffffffffu, sum0, 1);
        sum0 += __shfl_xor_sync(0xffffffffu, sum0, 2);
        sum1 += __shfl_xor_sync(0xffffffffu, sum1, 1);
        sum1 += __shfl_xor_sync(0xffffffffu, sum1, 2);

        const float al0 = __expf(m0 - mn0), al1 = __expf(m1 - mn1);
        m0 = mn0; m1 = mn1;
        l0 = l0 * al0 + sum0;
        l1 = l1 * al1 + sum1;
        #pragma unroll
        for (int n = 0; n < 16; n++) {
            oacc[n][0] *= al0; oacc[n][1] *= al0;
            oacc[n][2] *= al1; oacc[n][3] *= al1;
        }

        CP_WAIT(2);              // V_kt complete
        __syncthreads();
        loadK((kt + 2) % AT_NT, cur);

        const uint32_t vb = sb + AST(cur);

        // ---- O += P V  (128 keys) ----
        #pragma unroll
        for (int kk = 0; kk < 8; kk++) {
            uint32_t pah[4] = {ph[2*kk][0], ph[2*kk][1], ph[2*kk+1][0], ph[2*kk+1][1]};
            #pragma unroll
            for (int p = 0; p < 8; p++) {
                uint32_t vh4[4];
                ldmx4t(vh4, vb + AV_H + asw(kk * 16 + v_row, 2 * p + v_cb));
                mma_fp16(oacc[2*p],   pah, vh4);
                mma_fp16(oacc[2*p+1], pah, vh4 + 2);
            }
        }
    }

    // ---- epilogue: normalize, write fp16 ----
    const float inv0 = 1.f / l0, inv1 = 1.f / l1;
    const int rr = lane >> 2, c2 = (lane & 3) * 2;
    const size_t row0 = tok0 + warp * 16 + rr, row1 = row0 + 8;
    #pragma unroll
    for (int n = 0; n < 16; n++) {
        int col = h * DK + n * 8 + c2;
        *(uint32_t*)&oh_g[row0 * D_MODEL + col] = pack2h(oacc[n][0] * inv0, oacc[n][1] * inv0);
        *(uint32_t*)&oh_g[row1 * D_MODEL + col] = pack2h(oacc[n][2] * inv1, oacc[n][3] * inv1);
    }
}

// ---------------------------------------------------------------------------
extern "C" void kernel_launch(void* const* d_in, const int* in_sizes, int n_in,
                              void* d_out, int out_size)
{
    const float* x    = (const float*)d_in[0];
    const float* Wqkv = (const float*)d_in[1];
    const float* bqkv = (const float*)d_in[2];
    const float* Wout = (const float*)d_in[3];
    const float* bout = (const float*)d_in[4];
    float* out = (float*)d_out;

    __half *qkh, *ah, *wqh, *woh;
    cudaGetSymbolAddress((void**)&qkh, g_qkv_hi);
    cudaGetSymbolAddress((void**)&ah, g_a_hi);
    cudaGetSymbolAddress((void**)&wqh, g_wq_h);
    cudaGetSymbolAddress((void**)&woh, g_wo_h);

    cudaFuncSetAttribute((const void*)gemm_hmma<true>,
                         cudaFuncAttributeMaxDynamicSharedMemorySize, GEMM_SMEM);
    cudaFuncSetAttribute((const void*)gemm_hmma<false>,
                         cudaFuncAttributeMaxDynamicSharedMemorySize, GEMM_SMEM);
    cudaFuncSetAttribute(attn_hmma, cudaFuncAttributeMaxDynamicSharedMemorySize, ATTN_SMEM);

    // 0) fused preprocessing: x convert + both weight transposes, one launch
    prep_kernel<<<PREP_BLK, dim3(32, 8)>>>(x, ah, Wqkv, wqh, Wout, woh);

    // 1) QKV projection: fp16 output
    gemm_hmma<true><<<dim3(QKV_N / 128, ROWS / 128), 128, GEMM_SMEM>>>(
        ah, wqh, bqkv, nullptr, qkh, ROWS, QKV_N, D_MODEL);

    // 2) attention -> attn-out fp16
    attn_hmma<<<dim3(SEQ / AT_BQ, BATCH * NHEADS), 256, ATTN_SMEM>>>(qkh, ah);

    // 3) out-projection: fp32 output
    gemm_hmma<false><<<dim3(D_MODEL / 128, ROWS / 128), 128, GEMM_SMEM>>>(
        ah, woh, bout, out, nullptr, ROWS, D_MODEL, D_MODEL);
}